// round 3
// baseline (speedup 1.0000x reference)
#include <cuda_runtime.h>
#include <cstdint>

// Problem shape (fixed for this dataset entry)
#define BATCH   2
#define NPTS    1024
#define CNUM    32      // radial basis centers
#define DIN     8
#define DOUT    8

#define NSPLIT  8               // b-range split for parallelism
#define CHUNK   (NPTS / NSPLIT) // 128 b-points per split
#define TILE_A  32              // a-points per block (x 8 cg-threads = 256 threads)

// Scratch for partial S[s][z][a][c][j]  (8 * 2 * 1024 * 32 * 8 floats = 16 MB)
__device__ float g_S[(size_t)NSPLIT * BATCH * NPTS * CNUM * DIN];

__device__ __forceinline__ float ex2_approx(float x) {
    float y; asm("ex2.approx.f32 %0, %1;" : "=f"(y) : "f"(x)); return y;
}
__device__ __forceinline__ float sqrt_approx(float x) {
    float y; asm("sqrt.approx.f32 %0, %1;" : "=f"(y) : "f"(x)); return y;
}

// ---------------------------------------------------------------------------
// Stage 1: S[z,a,c,j] = sum_b exp(-((d_ab/width) - c)^2) * feat[z,b,j]
// Block: 256 threads = TILE_A(32) a-points x 8 c-groups (4 centers each).
// Grid:  (NPTS/TILE_A, NSPLIT, BATCH)
// ---------------------------------------------------------------------------
__global__ __launch_bounds__(256)
void conv_stage1(const float* __restrict__ feat, const float* __restrict__ geo)
{
    __shared__ float4 gb[CHUNK];       // geometry of b-chunk (padded to float4)
    __shared__ float4 fb[CHUNK * 2];   // features of b-chunk (8 floats = 2 float4)

    const int z  = blockIdx.z;
    const int s  = blockIdx.y;
    const int a0 = blockIdx.x * TILE_A;
    const int tx = threadIdx.x;
    const int b0 = s * CHUNK;

    // Stage feat chunk: CHUNK*2 float4s, one per thread
    {
        const float4* fsrc = (const float4*)(feat + (size_t)z * NPTS * DIN);
        for (int i = tx; i < CHUNK * 2; i += 256)
            fb[i] = fsrc[b0 * 2 + i];
        for (int i = tx; i < CHUNK; i += 256) {
            const float* g = geo + ((size_t)z * NPTS + b0 + i) * 3;
            gb[i] = make_float4(g[0], g[1], g[2], 0.0f);
        }
    }
    __syncthreads();

    const int a_local = tx >> 3;
    const int cg      = tx & 7;        // owns centers [4*cg, 4*cg+4)
    const int a       = a0 + a_local;

    const float* ga = geo + ((size_t)z * NPTS + a) * 3;
    const float ax = ga[0], ay = ga[1], az = ga[2];

    const float invw      = 31.0f / 3.5f;           // 1/width, width = R_MAX/(C-1)
    const float NEG_LOG2E = -1.4426950408889634f;   // exp(-x) = 2^(-x*log2e)
    const float c0 = (float)(cg * 4);
    const float c1 = c0 + 1.0f, c2 = c0 + 2.0f, c3 = c0 + 3.0f;

    float acc[4][8];
#pragma unroll
    for (int k = 0; k < 4; ++k)
#pragma unroll
        for (int j = 0; j < 8; ++j) acc[k][j] = 0.0f;

#pragma unroll 2
    for (int b = 0; b < CHUNK; ++b) {
        float4 g = gb[b];                              // broadcast (uniform b)
        float dx = g.x - ax, dy = g.y - ay, dz = g.z - az;
        float d2 = fmaf(dx, dx, fmaf(dy, dy, fmaf(dz, dz, 1e-12f)));
        float u  = sqrt_approx(d2) * invw;             // d / width

        float t0 = u - c0, t1 = u - c1, t2 = u - c2, t3 = u - c3;
        float bs[4];
        bs[0] = ex2_approx(t0 * t0 * NEG_LOG2E);       // exp(-t^2)
        bs[1] = ex2_approx(t1 * t1 * NEG_LOG2E);
        bs[2] = ex2_approx(t2 * t2 * NEG_LOG2E);
        bs[3] = ex2_approx(t3 * t3 * NEG_LOG2E);

        float4 fA = fb[b * 2], fB = fb[b * 2 + 1];     // broadcast
        float f[8] = {fA.x, fA.y, fA.z, fA.w, fB.x, fB.y, fB.z, fB.w};

#pragma unroll
        for (int k = 0; k < 4; ++k)
#pragma unroll
            for (int j = 0; j < 8; ++j)
                acc[k][j] = fmaf(bs[k], f[j], acc[k][j]);
    }

    // Write 32 contiguous floats: S[s][z][a][cg*4 + k][j]
    float* outp = g_S + ((((size_t)s * BATCH + z) * NPTS + a) * (CNUM * DIN)) + cg * 32;
#pragma unroll
    for (int k = 0; k < 4; ++k) {
        ((float4*)outp)[k * 2]     = make_float4(acc[k][0], acc[k][1], acc[k][2], acc[k][3]);
        ((float4*)outp)[k * 2 + 1] = make_float4(acc[k][4], acc[k][5], acc[k][6], acc[k][7]);
    }
}

// ---------------------------------------------------------------------------
// Stage 2: out[z,a,i] = (1/sqrt(n_norm)) * sum_c sum_j W[c,i,j] * S_total[z,a,c,j]
// One block per (z,a). 256 threads reduce the 8 splits; 64 threads contract W.
// ---------------------------------------------------------------------------
__global__ __launch_bounds__(256)
void conv_stage2(const float* __restrict__ W, const int* __restrict__ nn,
                 float* __restrict__ out)
{
    __shared__ float ss[CNUM * DIN];          // 256 summed S values for this (z,a)
    __shared__ float wsh[CNUM * DOUT * DIN];  // 2048 floats of W
    __shared__ float partial[8][8];           // [i][part]

    const int za = blockIdx.x;                // z*NPTS + a
    const int tx = threadIdx.x;

    for (int i = tx; i < CNUM * DOUT * DIN; i += 256)
        wsh[i] = W[i];

    float v = 0.0f;
#pragma unroll
    for (int s = 0; s < NSPLIT; ++s)
        v += g_S[((size_t)s * BATCH * NPTS + za) * (CNUM * DIN) + tx];
    ss[tx] = v;
    __syncthreads();

    if (tx < 64) {
        const int i = tx & 7, part = tx >> 3;  // 8 output dims x 8 c-partitions
        float acc = 0.0f;
#pragma unroll
        for (int k = 0; k < 4; ++k) {
            const int c = part * 4 + k;
#pragma unroll
            for (int j = 0; j < 8; ++j)
                acc = fmaf(wsh[(c * 8 + i) * 8 + j], ss[c * 8 + j], acc);
        }
        partial[i][part] = acc;
    }
    __syncthreads();

    if (tx < 8) {
        // n_norm may be serialized as int32 or float32; disambiguate by bit pattern.
        int   raw = nn[0];
        float nf  = (raw > 0 && raw <= (1 << 26)) ? (float)raw : __int_as_float(raw);
        float scale = rsqrtf(nf);
        float r = 0.0f;
#pragma unroll
        for (int p = 0; p < 8; ++p) r += partial[tx][p];
        out[(size_t)za * DOUT + tx] = r * scale;
    }
}

// ---------------------------------------------------------------------------
extern "C" void kernel_launch(void* const* d_in, const int* in_sizes, int n_in,
                              void* d_out, int out_size)
{
    const float* feat = (const float*)d_in[0];  // [2,1024,8]
    const float* geo  = (const float*)d_in[1];  // [2,1024,3]
    const float* W    = (const float*)d_in[2];  // [32,8,8]
    const int*   nn   = (const int*)d_in[3];    // scalar n_norm

    dim3 g1(NPTS / TILE_A, NSPLIT, BATCH);      // (32, 8, 2) = 512 blocks
    conv_stage1<<<g1, 256>>>(feat, geo);

    conv_stage2<<<BATCH * NPTS, 256>>>(W, nn, (float*)d_out);
}